// round 6
// baseline (speedup 1.0000x reference)
#include <cuda_runtime.h>

// SocialCircleLayer: B=8192 rows, N=128 neighbors, T=8, P=8.
// R6: persistent single-wave grid (1184 CTAs = 148 SMs x 8) looping over rows.
// Removes ~6 wave transitions (~2.4k cyc each ~= 40% of wall time) and
// software-pipelines next-row LDGs across the barrier + phase-2 tail.
// Row logic identical to R5 (ballot masks + ffs-driven exact-read phase 2).

#define NNEI   128
#define PARTS  8
#define MU_F     1e-4f
#define CEPS_F   1e-4f
#define TWO_PI_F 6.283185307179586f
#define NSM    148
#define CTA_PER_SM 8

__device__ __forceinline__ float approx_len(float x2) {
    float r;
    asm("rsqrt.approx.f32 %0, %1;" : "=f"(r) : "f"(x2));
    float len = x2 * r;
    return (x2 > 0.0f) ? len : 0.0f;
}

__global__ __launch_bounds__(NNEI) void social_circle_kernel(
    const float* __restrict__ trajs,      // [B, 8, 2]
    const float* __restrict__ nei_trajs,  // [B, 128, 8, 2]
    float* __restrict__ out_sc,           // [B, 8, 3]
    float* __restrict__ out_dir,          // [B, 128]
    int B)
{
    const int n    = threadIdx.x;
    const int wid  = n >> 5;
    const int lane = n & 31;
    const int G    = gridDim.x;

    __shared__ float4   vals[2][NNEI];        // double-buffered {speed, dist, dir, -}
    __shared__ unsigned pmask[2][4][PARTS];   // [buf][src warp][partition]

    int b = blockIdx.x;
    if (b >= B) return;

    // prime the pipeline: loads for the first row
    const float* tb0 = trajs + (size_t)b * 16;
    float ox7 = tb0[14], oy7 = tb0[15];
    float ofx = tb0[0],  ofy = tb0[1];
    const float4* np4 = (const float4*)(nei_trajs + ((size_t)b * NNEI + n) * 16);
    float4 v0 = np4[0];
    float4 v1 = np4[1];
    float4 v2 = np4[2];
    float4 v3 = np4[3];

    int par = 0;
    for (;;) {
        const int bn = b + G;               // next row this CTA will process
        const bool more = (bn < B);

        // ---- phase 1: features for row b (in registers) ----
        const float ovx = ox7 - ofx;
        const float ovy = oy7 - ofy;
        const float obs_len = approx_len(ovx * ovx + ovy * ovy);

        const float ssum = (v0.x + v0.y + v0.z + v0.w)
                         + (v1.x + v1.y + v1.z + v1.w)
                         + (v2.x + v2.y + v2.z + v2.w)
                         + (v3.x + v3.y + v3.z + v3.w);
        const bool valid = (ssum != 0.0f);

        const float nvx = v3.z - v0.x;
        const float nvy = v3.w - v0.y;
        const float nei_len = approx_len(nvx * nvx + nvy * nvy);
        const float f_speed = __fdividef(nei_len + MU_F, obs_len + MU_F);

        const float px = v3.z - ox7;
        const float py = v3.w - oy7;
        const float f_dist = approx_len(px * px + py * py);

        float d = atan2f(py, px);
        if (d < 0.0f) d += TWO_PI_F;

        out_dir[(size_t)b * NNEI + n] = d;

        const int idx = (int)(d / (TWO_PI_F / PARTS));
        const int key = (valid && idx < PARTS) ? idx : -1;

        vals[par][n] = make_float4(f_speed, f_dist, d, 0.0f);

        unsigned mymask = 0;
        #pragma unroll
        for (int p = 0; p < PARTS; p++) {
            const unsigned m = __ballot_sync(0xffffffffu, key == p);
            if (lane == p) mymask = m;
        }
        if (lane < PARTS) pmask[par][wid][lane] = mymask;

        // ---- prefetch next row's data BEFORE the barrier (overlaps phase 2) ----
        if (more) {
            const float* tbn = trajs + (size_t)bn * 16;
            ofx = tbn[0];  ofy = tbn[1];
            ox7 = tbn[14]; oy7 = tbn[15];
            const float4* nn4 = (const float4*)(nei_trajs + ((size_t)bn * NNEI + n) * 16);
            v0 = nn4[0];
            v1 = nn4[1];
            v2 = nn4[2];
            v3 = nn4[3];
        }

        __syncthreads();

        // ---- phase 2: warp 0, thread = (partition p = n>>2, source warp r = n&3) ----
        if (n < 32) {
            const int p = n >> 2;
            const int r = n & 3;

            unsigned m = pmask[par][r][p];
            float cnt = (float)__popc(m);
            float s = 0.0f, dd = 0.0f, dir = 0.0f;
            const int base = r << 5;

            while (m) {
                const int j = __ffs(m) - 1;
                m &= m - 1;
                const float4 v = vals[par][base + j];
                s   += v.x;
                dd  += v.y;
                dir += v.z;
            }

            #pragma unroll
            for (int off = 2; off > 0; off >>= 1) {
                s   += __shfl_down_sync(0xffffffffu, s,   off, 4);
                dd  += __shfl_down_sync(0xffffffffu, dd,  off, 4);
                dir += __shfl_down_sync(0xffffffffu, dir, off, 4);
                cnt += __shfl_down_sync(0xffffffffu, cnt, off, 4);
            }

            const float inv = __fdividef(1.0f, cnt + CEPS_F);
            s   *= inv;
            dd  *= inv;
            dir *= inv;

            // redistribute so lanes 0..23 emit one coalesced 96B store
            const int p2  = (lane * 11) >> 5;   // lane/3 for lane<32
            const int f   = lane - p2 * 3;
            const int src = p2 << 2;
            const float a0 = __shfl_sync(0xffffffffu, s,   src);
            const float a1 = __shfl_sync(0xffffffffu, dd,  src);
            const float a2 = __shfl_sync(0xffffffffu, dir, src);
            const float outv = (f == 0) ? a0 : ((f == 1) ? a1 : a2);
            if (lane < PARTS * 3) {
                out_sc[(size_t)b * (PARTS * 3) + lane] = outv;
            }
        }

        if (!more) break;
        b = bn;
        par ^= 1;
    }
}

extern "C" void kernel_launch(void* const* d_in, const int* in_sizes, int n_in,
                              void* d_out, int out_size) {
    const float* trajs     = (const float*)d_in[0];
    const float* nei_trajs = (const float*)d_in[1];
    float* out = (float*)d_out;

    const int B = in_sizes[0] / 16;   // trajs is [B, 8, 2]

    float* out_sc  = out;                          // [B, 8, 3]
    float* out_dir = out + (size_t)B * PARTS * 3;  // [B, 128]

    int grid = NSM * CTA_PER_SM;                   // single wave, persistent loop
    if (grid > B) grid = B;

    social_circle_kernel<<<grid, NNEI>>>(trajs, nei_trajs, out_sc, out_dir, B);
}

// round 7
// speedup vs baseline: 1.0358x; 1.0358x over previous
#include <cuda_runtime.h>

// SocialCircleLayer: B=8192 rows, N=128 neighbors, T=8, P=8.
// R7: R6 persistent+prefetch kernel with the occupancy bug fixed:
// grid = 148 SMs x 16 CTAs (2048 thr/SM, the real concurrency ceiling),
// not x8. R6's regression traced entirely to occ 76%->43% from grid=1184.
// Prefetched next-row LDGs stay in flight across the barrier + phase-2 tail,
// raising DRAM duty cycle per CTA.

#define NNEI   128
#define PARTS  8
#define MU_F     1e-4f
#define CEPS_F   1e-4f
#define TWO_PI_F 6.283185307179586f
#define NSM    148
#define CTA_PER_SM 16

__device__ __forceinline__ float approx_len(float x2) {
    float r;
    asm("rsqrt.approx.f32 %0, %1;" : "=f"(r) : "f"(x2));
    float len = x2 * r;
    return (x2 > 0.0f) ? len : 0.0f;
}

__global__ __launch_bounds__(NNEI) void social_circle_kernel(
    const float* __restrict__ trajs,      // [B, 8, 2]
    const float* __restrict__ nei_trajs,  // [B, 128, 8, 2]
    float* __restrict__ out_sc,           // [B, 8, 3]
    float* __restrict__ out_dir,          // [B, 128]
    int B)
{
    const int n    = threadIdx.x;
    const int wid  = n >> 5;
    const int lane = n & 31;
    const int G    = gridDim.x;

    __shared__ float4   vals[2][NNEI];        // double-buffered {speed, dist, dir, -}
    __shared__ unsigned pmask[2][4][PARTS];   // [buf][src warp][partition]

    int b = blockIdx.x;
    if (b >= B) return;

    // prime the pipeline: loads for the first row
    const float* tb0 = trajs + (size_t)b * 16;
    float ox7 = tb0[14], oy7 = tb0[15];
    float ofx = tb0[0],  ofy = tb0[1];
    const float4* np4 = (const float4*)(nei_trajs + ((size_t)b * NNEI + n) * 16);
    float4 v0 = np4[0];
    float4 v1 = np4[1];
    float4 v2 = np4[2];
    float4 v3 = np4[3];

    int par = 0;
    for (;;) {
        const int bn = b + G;               // next row this CTA will process
        const bool more = (bn < B);

        // ---- phase 1: features for row b (in registers) ----
        const float ovx = ox7 - ofx;
        const float ovy = oy7 - ofy;
        const float obs_len = approx_len(ovx * ovx + ovy * ovy);

        const float ssum = (v0.x + v0.y + v0.z + v0.w)
                         + (v1.x + v1.y + v1.z + v1.w)
                         + (v2.x + v2.y + v2.z + v2.w)
                         + (v3.x + v3.y + v3.z + v3.w);
        const bool valid = (ssum != 0.0f);

        const float nvx = v3.z - v0.x;
        const float nvy = v3.w - v0.y;
        const float nei_len = approx_len(nvx * nvx + nvy * nvy);
        const float f_speed = __fdividef(nei_len + MU_F, obs_len + MU_F);

        const float px = v3.z - ox7;
        const float py = v3.w - oy7;
        const float f_dist = approx_len(px * px + py * py);

        float d = atan2f(py, px);
        if (d < 0.0f) d += TWO_PI_F;

        out_dir[(size_t)b * NNEI + n] = d;

        const int idx = (int)(d / (TWO_PI_F / PARTS));
        const int key = (valid && idx < PARTS) ? idx : -1;

        vals[par][n] = make_float4(f_speed, f_dist, d, 0.0f);

        unsigned mymask = 0;
        #pragma unroll
        for (int p = 0; p < PARTS; p++) {
            const unsigned m = __ballot_sync(0xffffffffu, key == p);
            if (lane == p) mymask = m;
        }
        if (lane < PARTS) pmask[par][wid][lane] = mymask;

        // ---- prefetch next row BEFORE the barrier (stays in flight
        //      through phase 2 + next iteration's compute) ----
        if (more) {
            const float* tbn = trajs + (size_t)bn * 16;
            ofx = tbn[0];  ofy = tbn[1];
            ox7 = tbn[14]; oy7 = tbn[15];
            const float4* nn4 = (const float4*)(nei_trajs + ((size_t)bn * NNEI + n) * 16);
            v0 = nn4[0];
            v1 = nn4[1];
            v2 = nn4[2];
            v3 = nn4[3];
        }

        __syncthreads();

        // ---- phase 2: warp 0, thread = (partition p = n>>2, source warp r = n&3) ----
        if (n < 32) {
            const int p = n >> 2;
            const int r = n & 3;

            unsigned m = pmask[par][r][p];
            float cnt = (float)__popc(m);
            float s = 0.0f, dd = 0.0f, dir = 0.0f;
            const int base = r << 5;

            while (m) {
                const int j = __ffs(m) - 1;
                m &= m - 1;
                const float4 v = vals[par][base + j];
                s   += v.x;
                dd  += v.y;
                dir += v.z;
            }

            #pragma unroll
            for (int off = 2; off > 0; off >>= 1) {
                s   += __shfl_down_sync(0xffffffffu, s,   off, 4);
                dd  += __shfl_down_sync(0xffffffffu, dd,  off, 4);
                dir += __shfl_down_sync(0xffffffffu, dir, off, 4);
                cnt += __shfl_down_sync(0xffffffffu, cnt, off, 4);
            }

            const float inv = __fdividef(1.0f, cnt + CEPS_F);
            s   *= inv;
            dd  *= inv;
            dir *= inv;

            // redistribute so lanes 0..23 emit one coalesced 96B store
            const int p2  = (lane * 11) >> 5;   // lane/3 for lane<32
            const int f   = lane - p2 * 3;
            const int src = p2 << 2;
            const float a0 = __shfl_sync(0xffffffffu, s,   src);
            const float a1 = __shfl_sync(0xffffffffu, dd,  src);
            const float a2 = __shfl_sync(0xffffffffu, dir, src);
            const float outv = (f == 0) ? a0 : ((f == 1) ? a1 : a2);
            if (lane < PARTS * 3) {
                out_sc[(size_t)b * (PARTS * 3) + lane] = outv;
            }
        }

        if (!more) break;
        b = bn;
        par ^= 1;
    }
}

extern "C" void kernel_launch(void* const* d_in, const int* in_sizes, int n_in,
                              void* d_out, int out_size) {
    const float* trajs     = (const float*)d_in[0];
    const float* nei_trajs = (const float*)d_in[1];
    float* out = (float*)d_out;

    const int B = in_sizes[0] / 16;   // trajs is [B, 8, 2]

    float* out_sc  = out;                          // [B, 8, 3]
    float* out_dir = out + (size_t)B * PARTS * 3;  // [B, 128]

    int grid = NSM * CTA_PER_SM;                   // fills 2048 thr/SM
    if (grid > B) grid = B;

    social_circle_kernel<<<grid, NNEI>>>(trajs, nei_trajs, out_sc, out_dir, B);
}

// round 8
// speedup vs baseline: 1.1542x; 1.1144x over previous
#include <cuda_runtime.h>

// SocialCircleLayer: B=8192 rows, N=128 neighbors, T=8, P=8.
// R8: R5 skeleton (best: 18.6us) with 2 rows per 256-thread CTA.
// Halves barrier count + CTA launch churn; phase-2 tails for both rows run
// concurrently (warp 0 -> row 0, warp 1 -> row 1), halving per-row dead time.
// Persistence abandoned: prefetch regs (48) capped occupancy (R6/R7 lesson).

#define NNEI   128
#define PARTS  8
#define ROWS_PER_CTA 2
#define MU_F     1e-4f
#define CEPS_F   1e-4f
#define TWO_PI_F 6.283185307179586f

__device__ __forceinline__ float approx_len(float x2) {
    float r;
    asm("rsqrt.approx.f32 %0, %1;" : "=f"(r) : "f"(x2));
    float len = x2 * r;
    return (x2 > 0.0f) ? len : 0.0f;
}

__global__ __launch_bounds__(NNEI * ROWS_PER_CTA) void social_circle_kernel(
    const float* __restrict__ trajs,      // [B, 8, 2]
    const float* __restrict__ nei_trajs,  // [B, 128, 8, 2]
    float* __restrict__ out_sc,           // [B, 8, 3]
    float* __restrict__ out_dir)          // [B, 128]
{
    const int n    = threadIdx.x;          // 0..255
    const int row  = n >> 7;               // 0 or 1 (which batch row in this CTA)
    const int ln   = n & 127;              // neighbor index within row
    const int wid  = (n >> 5) & 3;         // source warp within row
    const int lane = n & 31;

    const int b = blockIdx.x * ROWS_PER_CTA + row;

    __shared__ float4   vals[ROWS_PER_CTA][NNEI];      // {speed, dist, dir, -}
    __shared__ unsigned pmask[ROWS_PER_CTA][4][PARTS]; // [row][src warp][partition]

    // obs vector (uniform per row-half -> broadcast loads)
    const float* tb = trajs + (size_t)b * 16;
    const float ox7 = tb[14], oy7 = tb[15];
    const float ovx = ox7 - tb[0];
    const float ovy = oy7 - tb[1];
    const float obs_len = approx_len(ovx * ovx + ovy * ovy);

    // 64B contiguous per thread
    const float4* np4 = (const float4*)(nei_trajs + ((size_t)b * NNEI + ln) * 16);
    const float4 v0 = np4[0];
    const float4 v1 = np4[1];
    const float4 v2 = np4[2];
    const float4 v3 = np4[3];

    // validity: sum of all 16 coords != 0
    const float ssum = (v0.x + v0.y + v0.z + v0.w)
                     + (v1.x + v1.y + v1.z + v1.w)
                     + (v2.x + v2.y + v2.z + v2.w)
                     + (v3.x + v3.y + v3.z + v3.w);
    const bool valid = (ssum != 0.0f);

    // displacement t=7 - t=0
    const float nvx = v3.z - v0.x;
    const float nvy = v3.w - v0.y;
    const float nei_len = approx_len(nvx * nvx + nvy * nvy);
    const float f_speed = __fdividef(nei_len + MU_F, obs_len + MU_F);

    // relative position at final step
    const float px = v3.z - ox7;
    const float py = v3.w - oy7;
    const float f_dist = approx_len(px * px + py * py);

    // f_direction = mod(atan2(py, px), 2*pi)
    float d = atan2f(py, px);
    if (d < 0.0f) d += TWO_PI_F;

    out_dir[(size_t)b * NNEI + ln] = d;

    // bucket key: exact IEEE division (boundary-sensitive); invalid or
    // idx==PARTS (d rounds to 2*pi) -> -1 (excluded everywhere)
    const int idx = (int)(d / (TWO_PI_F / PARTS));
    const int key = (valid && idx < PARTS) ? idx : -1;

    vals[row][ln] = make_float4(f_speed, f_dist, d, 0.0f);

    // membership bitmasks on the VOTE pipe; lane p keeps partition p's mask
    unsigned mymask = 0;
    #pragma unroll
    for (int p = 0; p < PARTS; p++) {
        const unsigned m = __ballot_sync(0xffffffffu, key == p);
        if (lane == p) mymask = m;
    }
    if (lane < PARTS) pmask[row][wid][lane] = mymask;
    __syncthreads();

    // Phase 2: warp w (w < ROWS_PER_CTA) reduces row w.
    // lane = (partition p = lane>>2, source warp r = lane&3).
    if (n < 32 * ROWS_PER_CTA) {
        const int r2   = n >> 5;           // row this warp reduces
        const int p    = lane >> 2;
        const int r    = lane & 3;
        const int bb   = blockIdx.x * ROWS_PER_CTA + r2;

        unsigned m = pmask[r2][r][p];
        float cnt = (float)__popc(m);
        float s = 0.0f, dd = 0.0f, dir = 0.0f;
        const int base = r << 5;

        while (m) {                         // each 16B value read exactly once
            const int j = __ffs(m) - 1;
            m &= m - 1;
            const float4 v = vals[r2][base + j];
            s   += v.x;
            dd  += v.y;
            dir += v.z;
        }

        // width-4 shuffle tree (4 source warps per partition)
        #pragma unroll
        for (int off = 2; off > 0; off >>= 1) {
            s   += __shfl_down_sync(0xffffffffu, s,   off, 4);
            dd  += __shfl_down_sync(0xffffffffu, dd,  off, 4);
            dir += __shfl_down_sync(0xffffffffu, dir, off, 4);
            cnt += __shfl_down_sync(0xffffffffu, cnt, off, 4);
        }

        const float inv = __fdividef(1.0f, cnt + CEPS_F);
        s   *= inv;
        dd  *= inv;
        dir *= inv;

        // redistribute so lanes 0..23 emit one coalesced 96B store per row
        const int p2  = (lane * 11) >> 5;   // lane/3 for lane<32
        const int f   = lane - p2 * 3;
        const int src = p2 << 2;            // leader lane of partition p2
        const float a0 = __shfl_sync(0xffffffffu, s,   src);
        const float a1 = __shfl_sync(0xffffffffu, dd,  src);
        const float a2 = __shfl_sync(0xffffffffu, dir, src);
        const float outv = (f == 0) ? a0 : ((f == 1) ? a1 : a2);
        if (lane < PARTS * 3) {
            out_sc[(size_t)bb * (PARTS * 3) + lane] = outv;
        }
    }
}

extern "C" void kernel_launch(void* const* d_in, const int* in_sizes, int n_in,
                              void* d_out, int out_size) {
    const float* trajs     = (const float*)d_in[0];
    const float* nei_trajs = (const float*)d_in[1];
    float* out = (float*)d_out;

    const int B = in_sizes[0] / 16;   // trajs is [B, 8, 2]

    float* out_sc  = out;                          // [B, 8, 3]
    float* out_dir = out + (size_t)B * PARTS * 3;  // [B, 128]

    social_circle_kernel<<<B / ROWS_PER_CTA, NNEI * ROWS_PER_CTA>>>(
        trajs, nei_trajs, out_sc, out_dir);
}